// round 16
// baseline (speedup 1.0000x reference)
#include <cuda_runtime.h>
#include <cuda_bf16.h>
#include <math.h>
#include <stdint.h>

// Problem constants
#define B_   8
#define T_   4096
#define NH_  16
#define MD_  64
#define FF_  256
#define HEADS_ 4
#define DH_  16
#define PEH_ 32
#define BT_  (B_ * T_)        // 32768

// ---------------- mma.sync helpers (base ISA, works on sm_103) ----------
__device__ __forceinline__ uint32_t smem_u32(const void* p) {
    uint32_t a;
    asm("{ .reg .u64 t; cvta.to.shared.u64 t, %1; cvt.u32.u64 %0, t; }"
        : "=r"(a) : "l"(p));
    return a;
}
__device__ __forceinline__ void ldm_x4(uint32_t* r, uint32_t addr) {
    asm volatile("ldmatrix.sync.aligned.m8n8.x4.shared.b16 {%0,%1,%2,%3}, [%4];"
                 : "=r"(r[0]), "=r"(r[1]), "=r"(r[2]), "=r"(r[3]) : "r"(addr));
}
__device__ __forceinline__ void mma_bf16(float* c, const uint32_t* a,
                                         const uint32_t* b) {
    asm volatile(
        "mma.sync.aligned.m16n8k16.row.col.f32.bf16.bf16.f32 "
        "{%0,%1,%2,%3}, {%4,%5,%6,%7}, {%8,%9}, {%0,%1,%2,%3};"
        : "+f"(c[0]), "+f"(c[1]), "+f"(c[2]), "+f"(c[3])
        : "r"(a[0]), "r"(a[1]), "r"(a[2]), "r"(a[3]), "r"(b[0]), "r"(b[1]));
}
#define SW(o) ((uint32_t)(o) ^ (((uint32_t)(o) >> 3) & 0x70u))

// ---------------- device scratch (static, no allocations) ----------------
__device__ int   g_idx[T_ * NH_];
__device__ float g_c1[T_ * NH_];
__device__ float g_c2[T_ * NH_];
__device__ float g_bias[(size_t)T_ * HEADS_ * NH_ * NH_];   // 16 MB
__device__ __nv_bfloat16 g_xn_hi[(size_t)BT_ * MD_];        // 4 MB
__device__ __nv_bfloat16 g_xn_lo[(size_t)BT_ * MD_];        // 4 MB
__device__ __nv_bfloat16 g_xu_hi[(size_t)BT_ * 1024];       // 64 MB
__device__ __nv_bfloat16 g_xu_lo[(size_t)BT_ * 1024];       // 64 MB
__device__ __nv_bfloat16 g_w1t_hi[1024 * 1024];             // Wu1^T hi  2 MB
__device__ __nv_bfloat16 g_w1t_lo[1024 * 1024];             // Wu1^T lo  2 MB
__device__ __nv_bfloat16 g_wqkvoT_hi[4 * 64 * 64];          // Wq/Wk/Wv/Wo ^T
__device__ __nv_bfloat16 g_wqkvoT_lo[4 * 64 * 64];
__device__ __nv_bfloat16 g_wn1T_hi[256 * 64];               // Wn1^T
__device__ __nv_bfloat16 g_wn1T_lo[256 * 64];

// =========================================================================
// Kernel 1: LayerNorm over x rows -> bf16 hi/lo split
// =========================================================================
__global__ void k_ln1(const float* __restrict__ x,
                      const float* __restrict__ g1,
                      const float* __restrict__ be1)
{
    int row  = blockIdx.x * 8 + (threadIdx.x >> 5);
    int lane = threadIdx.x & 31;
    const float* xr = x + (size_t)row * 64;
    float a = xr[lane], b = xr[lane + 32];
    float s = a + b, s2 = a * a + b * b;
    #pragma unroll
    for (int o = 16; o; o >>= 1) {
        s  += __shfl_xor_sync(0xffffffffu, s, o);
        s2 += __shfl_xor_sync(0xffffffffu, s2, o);
    }
    float m = s * (1.0f / 64.0f);
    float v = s2 * (1.0f / 64.0f) - m * m;
    float r = rsqrtf(v + 1e-5f);
    size_t base = (size_t)row * 64;
    float v0 = (a - m) * r * g1[lane]      + be1[lane];
    float v1 = (b - m) * r * g1[lane + 32] + be1[lane + 32];
    __nv_bfloat16 h0 = __float2bfloat16(v0);
    __nv_bfloat16 h1 = __float2bfloat16(v1);
    g_xn_hi[base + lane]      = h0;
    g_xn_lo[base + lane]      = __float2bfloat16(v0 - __bfloat162float(h0));
    g_xn_hi[base + lane + 32] = h1;
    g_xn_lo[base + lane + 32] = __float2bfloat16(v1 - __bfloat162float(h1));
}

// =========================================================================
// Kernel 2: top-16 nearest neighbors per t (matches jax.lax.top_k order)
// =========================================================================
__global__ void k_topk(const float* __restrict__ c1,
                       const float* __restrict__ c2)
{
    __shared__ unsigned long long res[4][16];
    int warp = threadIdx.x >> 5, lane = threadIdx.x & 31;
    int t = blockIdx.x * 4 + warp;
    float c1t = c1[t], c2t = c2[t];

    unsigned long long best[16];
    #pragma unroll
    for (int i = 0; i < 16; i++) best[i] = 0xFFFFFFFFFFFFFFFFull;

    for (int s = lane; s < T_; s += 32) {
        float d1 = __fadd_rn(c1[s], -c1t);
        float d2 = __fadd_rn(c2[s], -c2t);
        float dist = __fadd_rn(__fmul_rn(d1, d1), __fmul_rn(d2, d2));
        unsigned long long key =
            ((unsigned long long)__float_as_uint(dist) << 32) | (unsigned)s;
        if (key < best[15]) {
            int p = 15;
            while (p > 0 && key < best[p - 1]) { best[p] = best[p - 1]; p--; }
            best[p] = key;
        }
    }
    int p = 0;
    for (int r = 0; r < 16; r++) {
        unsigned long long cand = (p < 16) ? best[p] : 0xFFFFFFFFFFFFFFFFull;
        unsigned long long m = cand;
        #pragma unroll
        for (int o = 16; o; o >>= 1) {
            unsigned long long other = __shfl_xor_sync(0xffffffffu, m, o);
            if (other < m) m = other;
        }
        if (cand == m) p++;
        if (lane == 0) res[warp][r] = m;
    }
    __syncwarp();
    if (lane < 16) {
        unsigned long long key = res[warp][lane];
        int s = (int)(key & 0xFFFFFFFFu);
        g_idx[t * 16 + lane] = s;
        g_c1[t * 16 + lane] = __fadd_rn(c1[s], -c1t);
        g_c2[t * 16 + lane] = __fadd_rn(c2[s], -c2t);
    }
}

// =========================================================================
// Kernel 3: relative-position bias MLP  -> g_bias[t][h][i][j]
// =========================================================================
__global__ void k_bias(const float* __restrict__ Wp1, const float* __restrict__ bp1,
                       const float* __restrict__ Wp2, const float* __restrict__ bp2)
{
    __shared__ float sW1[64], sB1[32], sW2[128], sB2[4], sc1[16], sc2[16];
    int t = blockIdx.x, tid = threadIdx.x;
    if (tid < 64)  sW1[tid] = Wp1[tid];
    if (tid < 32)  sB1[tid] = bp1[tid];
    if (tid < 128) sW2[tid] = Wp2[tid];
    if (tid < 4)   sB2[tid] = bp2[tid];
    if (tid < 16) { sc1[tid] = g_c1[t * 16 + tid]; sc2[tid] = g_c2[t * 16 + tid]; }
    __syncthreads();

    int i = tid >> 4, j = tid & 15;
    float p0 = sc1[i] - sc1[j];
    float p1 = sc2[i] - sc2[j];
    float o0 = sB2[0], o1 = sB2[1], o2 = sB2[2], o3 = sB2[3];
    #pragma unroll
    for (int k = 0; k < 32; k++) {
        float h = fmaf(p0, sW1[k], fmaf(p1, sW1[32 + k], sB1[k]));
        h = (h >= 0.0f) ? h : 0.2f * h;
        o0 = fmaf(h, sW2[k * 4 + 0], o0);
        o1 = fmaf(h, sW2[k * 4 + 1], o1);
        o2 = fmaf(h, sW2[k * 4 + 2], o2);
        o3 = fmaf(h, sW2[k * 4 + 3], o3);
    }
    int base = ((t * 4) * 16 + i) * 16 + j;
    g_bias[base]       = o0;
    g_bias[base + 256] = o1;
    g_bias[base + 512] = o2;
    g_bias[base + 768] = o3;
}

// =========================================================================
// Kernel 3b: transpose + bf16-split Wu1 (head) -> g_w1t_hi/lo  [j][k]
// =========================================================================
__global__ void k_split(const float* __restrict__ Wu1)
{
    __shared__ float tbuf[32][33];
    int bx = blockIdx.x, by = blockIdx.y;
    int tx = threadIdx.x & 31, ty = threadIdx.x >> 5;
    #pragma unroll
    for (int i = 0; i < 4; i++) {
        int r = by * 32 + ty + i * 8;
        tbuf[ty + i * 8][tx] = Wu1[(size_t)r * 1024 + bx * 32 + tx];
    }
    __syncthreads();
    #pragma unroll
    for (int i = 0; i < 4; i++) {
        int j = bx * 32 + ty + i * 8;
        int k = by * 32 + tx;
        float v = tbuf[tx][ty + i * 8];
        __nv_bfloat16 hi = __float2bfloat16(v);
        g_w1t_hi[(size_t)j * 1024 + k] = hi;
        g_w1t_lo[(size_t)j * 1024 + k] = __float2bfloat16(v - __bfloat162float(hi));
    }
}

// =========================================================================
// Kernel 3c: transpose + split Wq/Wk/Wv/Wo (64x64) and Wn1 (64x256)
// =========================================================================
__global__ void k_prep_w(const float* __restrict__ Wq, const float* __restrict__ Wk,
                         const float* __restrict__ Wv, const float* __restrict__ Wo,
                         const float* __restrict__ Wn1)
{
    int m = blockIdx.x;
    if (m < 4) {
        const float* W = (m == 0) ? Wq : (m == 1) ? Wk : (m == 2) ? Wv : Wo;
        for (int idx = threadIdx.x; idx < 4096; idx += 256) {
            int j = idx >> 6, k = idx & 63;
            float v = W[k * 64 + j];
            __nv_bfloat16 hi = __float2bfloat16(v);
            g_wqkvoT_hi[m * 4096 + j * 64 + k] = hi;
            g_wqkvoT_lo[m * 4096 + j * 64 + k] =
                __float2bfloat16(v - __bfloat162float(hi));
        }
    } else {
        for (int idx = threadIdx.x; idx < 16384; idx += 256) {
            int j = idx >> 6, k = idx & 63;
            float v = Wn1[k * 256 + j];
            __nv_bfloat16 hi = __float2bfloat16(v);
            g_wn1T_hi[j * 64 + k] = hi;
            g_wn1T_lo[j * 64 + k] = __float2bfloat16(v - __bfloat162float(hi));
        }
    }
}

// =========================================================================
// 3-term bf16-split mma: C[128x64] += A[128x64] @ B^T, warp tile 32x32
// =========================================================================
__device__ __forceinline__ void mma3_32x32(
    uint32_t sb, int aH, int aL, int bH, int bL,
    int warp_m, int warp_n, int lm_r, int lm_k, int lb_r, int lb_k,
    float acc[2][4][4])
{
    #pragma unroll
    for (int k16 = 0; k16 < 4; k16++) {
        int kb = k16 * 32;
        uint32_t ah[2][4], bf[4][2], t4[4];
        #pragma unroll
        for (int mi = 0; mi < 2; mi++)
            ldm_x4(ah[mi], sb + aH +
                   SW((warp_m * 32 + mi * 16 + lm_r) * 128 + kb + lm_k * 2));
        #pragma unroll
        for (int n2 = 0; n2 < 2; n2++) {
            ldm_x4(t4, sb + bH +
                   SW((warp_n * 32 + n2 * 16 + lb_r) * 128 + kb + lb_k * 2));
            bf[n2 * 2][0] = t4[0]; bf[n2 * 2][1] = t4[1];
            bf[n2 * 2 + 1][0] = t4[2]; bf[n2 * 2 + 1][1] = t4[3];
        }
        #pragma unroll
        for (int mi = 0; mi < 2; mi++)
            #pragma unroll
            for (int ni = 0; ni < 4; ni++)
                mma_bf16(acc[mi][ni], ah[mi], bf[ni]);
        uint32_t al[2][4];
        #pragma unroll
        for (int mi = 0; mi < 2; mi++)
            ldm_x4(al[mi], sb + aL +
                   SW((warp_m * 32 + mi * 16 + lm_r) * 128 + kb + lm_k * 2));
        #pragma unroll
        for (int mi = 0; mi < 2; mi++)
            #pragma unroll
            for (int ni = 0; ni < 4; ni++)
                mma_bf16(acc[mi][ni], al[mi], bf[ni]);
        #pragma unroll
        for (int n2 = 0; n2 < 2; n2++) {
            ldm_x4(t4, sb + bL +
                   SW((warp_n * 32 + n2 * 16 + lb_r) * 128 + kb + lb_k * 2));
            bf[n2 * 2][0] = t4[0]; bf[n2 * 2][1] = t4[1];
            bf[n2 * 2 + 1][0] = t4[2]; bf[n2 * 2 + 1][1] = t4[3];
        }
        #pragma unroll
        for (int mi = 0; mi < 2; mi++)
            #pragma unroll
            for (int ni = 0; ni < 4; ni++)
                mma_bf16(acc[mi][ni], ah[mi], bf[ni]);
    }
}

// =========================================================================
// Kernel 4: fused attention block, mma-based, 8 (b,t) tiles per iteration
// =========================================================================
#define AT_XGH  0
#define AT_XGL  16384
#define AT_AVH  32768
#define AT_AVL  49152
#define AT_Q    65536
#define AT_K    98304
#define AT_V    131072
#define AT_WBH  163840
#define AT_WBL  172032
#define AT_PRM  180224
#define AT_SMEM 190464
// phase-overlapped aliases
#define AT_Y    32768      // fp32 over AVH/AVL
#define AT_ZH   0          // over XGH
#define AT_ZL   16384      // over XGL
#define AT_W1H  65536      // over Q
#define AT_W1L  98304      // over K
#define AT_ZF   131072     // over V

__global__ void __launch_bounds__(256) k_attn_mma(
    const float* __restrict__ bq, const float* __restrict__ bk,
    const float* __restrict__ bv, const float* __restrict__ logit_scale,
    const float* __restrict__ bo,
    const float* __restrict__ g2, const float* __restrict__ be2,
    const float* __restrict__ bn1, const float* __restrict__ Wn2,
    const float* __restrict__ bn2,
    const float* __restrict__ g3, const float* __restrict__ be3)
{
    extern __shared__ char smc[];
    uint32_t sb = smem_u32(smc);
    int tid = threadIdx.x, wid = tid >> 5, lane = tid & 31;
    int warp_m = wid & 3, warp_n = wid >> 2;

    float* P    = (float*)(smc + AT_PRM);
    int*   sIdx = (int*)(P + 904);
    float* sQIN = P + 1032;
    float* sKIN = P + 1544;
    float* sRed = P + 2056;
    float* sR   = P + 2312;

    if (tid < 64) {
        P[tid]       = bq[tid];
        P[64 + tid]  = bk[tid];
        P[128 + tid] = bv[tid];
        P[192 + tid] = bo[tid];
        P[768 + tid] = g2[tid];
        P[832 + tid] = be2[tid];
    }
    P[256 + tid] = bn1[tid];
    P[512 + tid] = Wn2[tid];
    if (tid < 4) P[896 + tid] = expf(fminf(logit_scale[tid], logf(100.0f)));
    if (tid == 0) P[900] = bn2[0];
    __syncthreads();

    int lm_r = (lane & 7) + ((lane >> 3) & 1) * 8;
    int lm_k = (lane >> 4) * 8;
    int lb_r = (lane & 7) + ((lane >> 4) & 1) * 8;
    int lb_k = ((lane >> 3) & 1) * 8;

    float* sQ  = (float*)(smc + AT_Q);
    float* sK  = (float*)(smc + AT_K);
    float* sV  = (float*)(smc + AT_V);
    float* sY  = (float*)(smc + AT_Y);
    float* sZF = (float*)(smc + AT_ZF);

    for (int bi = blockIdx.x; bi < BT_ / 8; bi += gridDim.x) {
        int b = (bi * 8) >> 12;

        if (tid < 128) {
            int tl = tid >> 4, n = tid & 15;
            int t = (bi * 8 + tl) & (T_ - 1);
            sIdx[tid] = g_idx[t * 16 + n];
        }
        __syncthreads();

        // ---- gather 128 rows of xn (bf16 hi/lo, swizzled) ----
        #pragma unroll
        for (int v = 0; v < 4; v++) {
            int c = tid + v * 256;
            int r = c >> 3, k8 = c & 7;
            size_t src = (size_t)(b * T_ + sIdx[r]) * 64 + k8 * 8;
            uint32_t d = SW(r * 128 + k8 * 16);
            *(uint4*)(smc + AT_XGH + d) = *(const uint4*)&g_xn_hi[src];
            *(uint4*)(smc + AT_XGL + d) = *(const uint4*)&g_xn_lo[src];
        }
        __syncthreads();

        // ---- QKV projections (mma) ----
        #pragma unroll 1
        for (int m = 0; m < 3; m++) {
            #pragma unroll
            for (int v = 0; v < 2; v++) {
                int c = tid + v * 256;
                int r = c >> 3, k8 = c & 7;
                uint32_t d = SW(r * 128 + k8 * 16);
                *(uint4*)(smc + AT_WBH + d) =
                    *(const uint4*)&g_wqkvoT_hi[m * 4096 + r * 64 + k8 * 8];
                *(uint4*)(smc + AT_WBL + d) =
                    *(const uint4*)&g_wqkvoT_lo[m * 4096 + r * 64 + k8 * 8];
            }
            __syncthreads();

            float acc[2][4][4];
            #pragma unroll
            for (int mi = 0; mi < 2; mi++)
                #pragma unroll
                for (int ni = 0; ni < 4; ni++)
                    #pragma unroll
                    for (int e = 0; e < 4; e++) acc[mi][ni][e] = 0.0f;
            mma3_32x32(sb, AT_XGH, AT_XGL, AT_WBH, AT_WBL,
                       warp_m, warp_n, lm_r, lm_k, lb_r, lb_k, acc);

            float* dst = (m == 0) ? sQ : (m == 1) ? sK : sV;
            const float* bias = P + m * 64;
            #pragma unroll
            for (int mi = 0; mi < 2; mi++)
                #pragma unroll
                for (int ni = 0; ni < 4; ni++)
                    #pragma unroll
                    for (int e = 0; e < 4; e++) {
                        int row = warp_m * 32 + mi * 16 + (e >> 1) * 8 + (lane >> 2);
                        int col = warp_n * 32 + ni * 8 + (lane & 3) * 2 + (e & 1);
                        dst[row * 64 + col] = acc[mi][ni][e] + bias[col];
                    }
            __syncthreads();
        }

        // ---- q/k inverse norms (512 items) ----
        #pragma unroll
        for (int it = 0; it < 2; it++) {
            int q = tid + it * 256;
            int tl = q >> 6, h = (q >> 4) & 3, n = q & 15;
            int base = (tl * 16 + n) * 64 + h * 16;
            float sq = 0.f, sk = 0.f;
            #pragma unroll
            for (int d = 0; d < 16; d++) {
                float qv = sQ[base + d], kv = sK[base + d];
                sq = fmaf(qv, qv, sq); sk = fmaf(kv, kv, sk);
            }
            sQIN[q] = 1.0f / fmaxf(sqrtf(sq), 1e-6f);
            sKIN[q] = 1.0f / fmaxf(sqrtf(sk), 1e-6f);
        }
        __syncthreads();

        // ---- attention (512 items, AV -> bf16 hi/lo swizzled) ----
        #pragma unroll 1
        for (int it = 0; it < 2; it++) {
            int qi = tid + it * 256;
            int tl = qi >> 6, h = (qi >> 4) & 3, i = qi & 15;
            int t = (bi * 8 + tl) & (T_ - 1);
            int row = tl * 16 + i, hb = h * 16;
            float qr[16];
            #pragma unroll
            for (int d = 0; d < 16; d++) qr[d] = sQ[row * 64 + hb + d];
            float qs = sQIN[tl * 64 + hb + i] * P[896 + h];
            const float* bias_p = g_bias + (((size_t)t * 4 + h) * 16 + i) * 16;
            float sv[16], mx = -1e30f;
            #pragma unroll
            for (int j = 0; j < 16; j++) {
                const float* kp = sK + (tl * 16 + j) * 64 + hb;
                float s = 0.f;
                #pragma unroll
                for (int d = 0; d < 16; d++) s = fmaf(qr[d], kp[d], s);
                s = s * qs * sKIN[tl * 64 + hb + j] + bias_p[j];
                sv[j] = s; mx = fmaxf(mx, s);
            }
            float den = 0.f;
            #pragma unroll
            for (int j = 0; j < 16; j++) { sv[j] = expf(sv[j] - mx); den += sv[j]; }
            float inv = 1.0f / den;
            #pragma unroll
            for (int d = 0; d < 16; d++) {
                float a = 0.f;
                #pragma unroll
                for (int j = 0; j < 16; j++)
                    a = fmaf(sv[j], sV[(tl * 16 + j) * 64 + hb + d], a);
                a *= inv;
                __nv_bfloat16 hi = __float2bfloat16(a);
                uint32_t off = SW(row * 128 + (hb + d) * 2);
                *(__nv_bfloat16*)(smc + AT_AVH + off) = hi;
                *(__nv_bfloat16*)(smc + AT_AVL + off) =
                    __float2bfloat16(a - __bfloat162float(hi));
            }
        }
        __syncthreads();

        // ---- Wo projection (mma) + residual -> Y ----
        #pragma unroll
        for (int v = 0; v < 2; v++) {
            int c = tid + v * 256;
            int r = c >> 3, k8 = c & 7;
            uint32_t d = SW(r * 128 + k8 * 16);
            *(uint4*)(smc + AT_WBH + d) =
                *(const uint4*)&g_wqkvoT_hi[3 * 4096 + r * 64 + k8 * 8];
            *(uint4*)(smc + AT_WBL + d) =
                *(const uint4*)&g_wqkvoT_lo[3 * 4096 + r * 64 + k8 * 8];
        }
        __syncthreads();
        {
            float acc[2][4][4];
            #pragma unroll
            for (int mi = 0; mi < 2; mi++)
                #pragma unroll
                for (int ni = 0; ni < 4; ni++)
                    #pragma unroll
                    for (int e = 0; e < 4; e++) acc[mi][ni][e] = 0.0f;
            mma3_32x32(sb, AT_AVH, AT_AVL, AT_WBH, AT_WBL,
                       warp_m, warp_n, lm_r, lm_k, lb_r, lb_k, acc);
            __syncthreads();   // all AV reads complete before Y overwrite
            #pragma unroll
            for (int mi = 0; mi < 2; mi++)
                #pragma unroll
                for (int ni = 0; ni < 4; ni++)
                    #pragma unroll
                    for (int e = 0; e < 4; e++) {
                        int row = warp_m * 32 + mi * 16 + (e >> 1) * 8 + (lane >> 2);
                        int col = warp_n * 32 + ni * 8 + (lane & 3) * 2 + (e & 1);
                        uint32_t xo = SW(row * 128 + col * 2);
                        float xg =
                            __bfloat162float(*(__nv_bfloat16*)(smc + AT_XGH + xo)) +
                            __bfloat162float(*(__nv_bfloat16*)(smc + AT_XGL + xo));
                        sY[row * 64 + col] = acc[mi][ni][e] + P[192 + col] + xg;
                    }
        }
        // stage Wn1^T into Q/K region (dead) while Y settles
        #pragma unroll
        for (int v = 0; v < 8; v++) {
            int c = tid + v * 256;
            int r = c >> 3, k8 = c & 7;
            uint32_t d = SW(r * 128 + k8 * 16);
            *(uint4*)(smc + AT_W1H + d) = *(const uint4*)&g_wn1T_hi[r * 64 + k8 * 8];
            *(uint4*)(smc + AT_W1L + d) = *(const uint4*)&g_wn1T_lo[r * 64 + k8 * 8];
        }
        __syncthreads();

        // ---- LN2 -> Z (fp32 + bf16 hi/lo) ----
        {
            int row = tid >> 1, half = tid & 1;
            const float* yr = sY + row * 64 + half * 32;
            float s = 0.f, s2 = 0.f;
            #pragma unroll
            for (int c = 0; c < 32; c++) { float v = yr[c]; s += v; s2 = fmaf(v, v, s2); }
            s  += __shfl_xor_sync(0xffffffffu, s, 1);
            s2 += __shfl_xor_sync(0xffffffffu, s2, 1);
            float m = s * (1.0f / 64.0f);
            float var = s2 * (1.0f / 64.0f) - m * m;
            float rs = rsqrtf(var + 1e-5f);
            #pragma unroll
            for (int c = 0; c < 32; c++) {
                int col = half * 32 + c;
                float z = (yr[c] - m) * rs * P[768 + col] + P[832 + col];
                sZF[row * 64 + col] = z;
                __nv_bfloat16 hi = __float2bfloat16(z);
                uint32_t off = SW(row * 128 + col * 2);
                *(__nv_bfloat16*)(smc + AT_ZH + off) = hi;
                *(__nv_bfloat16*)(smc + AT_ZL + off) =
                    __float2bfloat16(z - __bfloat162float(hi));
            }
        }
        __syncthreads();

        // ---- FF1 (mma, 2 passes of 128 cols) + lrelu + Wn2 dot ----
        float orow[4] = {0.f, 0.f, 0.f, 0.f};
        #pragma unroll 1
        for (int p = 0; p < 2; p++) {
            float fa[2][8][4];
            #pragma unroll
            for (int mi = 0; mi < 2; mi++)
                #pragma unroll
                for (int ni = 0; ni < 8; ni++)
                    #pragma unroll
                    for (int e = 0; e < 4; e++) fa[mi][ni][e] = 0.0f;
            #pragma unroll
            for (int k16 = 0; k16 < 4; k16++) {
                int kb = k16 * 32;
                uint32_t ah[2][4], bf[8][2], t4[4];
                #pragma unroll
                for (int mi = 0; mi < 2; mi++)
                    ldm_x4(ah[mi], sb + AT_ZH +
                           SW((warp_m * 32 + mi * 16 + lm_r) * 128 + kb + lm_k * 2));
                #pragma unroll
                for (int n2 = 0; n2 < 4; n2++) {
                    ldm_x4(t4, sb + AT_W1H +
                           SW((p * 128 + warp_n * 64 + n2 * 16 + lb_r) * 128 + kb + lb_k * 2));
                    bf[n2 * 2][0] = t4[0]; bf[n2 * 2][1] = t4[1];
                    bf[n2 * 2 + 1][0] = t4[2]; bf[n2 * 2 + 1][1] = t4[3];
                }
                #pragma unroll
                for (int mi = 0; mi < 2; mi++)
                    #pragma unroll
                    for (int ni = 0; ni < 8; ni++)
                        mma_bf16(fa[mi][ni], ah[mi], bf[ni]);
                uint32_t al[2][4];
                #pragma unroll
                for (int mi = 0; mi < 2; mi++)
                    ldm_x4(al[mi], sb + AT_ZL +
                           SW((warp_m * 32 + mi * 16 + lm_r) * 128 + kb + lm_k * 2));
                #pragma unroll
                for (int mi = 0; mi < 2; mi++)
                    #pragma unroll
                    for (int ni = 0; ni < 8; ni++)
                        mma_bf16(fa[mi][ni], al[mi], bf[ni]);
                #pragma unroll
                for (int n2 = 0; n2 < 4; n2++) {
                    ldm_x4(t4, sb + AT_W1L +
                           SW((p * 128 + warp_n * 64 + n2 * 16 + lb_r) * 128 + kb + lb_k * 2));
                    bf[n2 * 2][0] = t4[0]; bf[n2 * 2][1] = t4[1];
                    bf[n2 * 2 + 1][0] = t4[2]; bf[n2 * 2 + 1][1] = t4[3];
                }
                #pragma unroll
                for (int mi = 0; mi < 2; mi++)
                    #pragma unroll
                    for (int ni = 0; ni < 8; ni++)
                        mma_bf16(fa[mi][ni], ah[mi], bf[ni]);
            }
            #pragma unroll
            for (int mi = 0; mi < 2; mi++)
                #pragma unroll
                for (int ni = 0; ni < 8; ni++)
                    #pragma unroll
                    for (int e = 0; e < 4; e++) {
                        int j = p * 128 + warp_n * 64 + ni * 8 + (lane & 3) * 2 + (e & 1);
                        float h = fa[mi][ni][e] + P[256 + j];
                        h = (h >= 0.0f) ? h : 0.2f * h;
                        orow[mi * 2 + (e >> 1)] = fmaf(P[512 + j], h, orow[mi * 2 + (e >> 1)]);
                    }
        }
        #pragma unroll
        for (int r4 = 0; r4 < 4; r4++) {
            float v = orow[r4];
            v += __shfl_xor_sync(0xffffffffu, v, 1);
            v += __shfl_xor_sync(0xffffffffu, v, 2);
            orow[r4] = v;
        }
        if ((lane & 3) == 0) {
            #pragma unroll
            for (int r4 = 0; r4 < 4; r4++) {
                int row = warp_m * 32 + (r4 >> 1) * 16 + (r4 & 1) * 8 + (lane >> 2);
                sRed[row * 2 + warp_n] = orow[r4];
            }
        }
        __syncthreads();
        if (tid < 128) {
            float rr = P[900] + sRed[tid * 2] + sRed[tid * 2 + 1];
            sR[tid] = (rr >= 0.0f) ? rr : 0.2f * rr;
        }
        __syncthreads();

        // ---- LN3 per tile (warp per tile) + write xu hi/lo ----
        {
            int tl = wid;
            int ti = bi * 8 + tl;
            float vals[32];
            float s = 0.f, s2 = 0.f;
            #pragma unroll
            for (int c = 0; c < 32; c++) {
                int i = lane * 32 + c;
                int n = i >> 6, d = i & 63;
                float v = sZF[(tl * 16 + n) * 64 + d] + sR[tl * 16 + n];
                vals[c] = v; s += v; s2 = fmaf(v, v, s2);
            }
            #pragma unroll
            for (int o = 16; o; o >>= 1) {
                s  += __shfl_xor_sync(0xffffffffu, s, o);
                s2 += __shfl_xor_sync(0xffffffffu, s2, o);
            }
            float m = s * (1.0f / 1024.0f);
            float var = s2 * (1.0f / 1024.0f) - m * m;
            float rs = rsqrtf(var + 1e-5f);
            #pragma unroll
            for (int c = 0; c < 32; c++) {
                int i = lane * 32 + c;
                float vv = (vals[c] - m) * rs * g3[i] + be3[i];
                __nv_bfloat16 hi = __float2bfloat16(vv);
                g_xu_hi[(size_t)ti * 1024 + i] = hi;
                g_xu_lo[(size_t)ti * 1024 + i] =
                    __float2bfloat16(vv - __bfloat162float(hi));
            }
        }
        __syncthreads();
    }
}

// =========================================================================
// Kernel 5: mma.sync bf16-split head GEMM + fused lrelu/Wu2 epilogue
// (unchanged from R9 passing version)
// =========================================================================
#define HM_SAH  0
#define HM_SAL  10240
#define HM_SBH  20480
#define HM_SBL  30720
#define HM_BU1  40960
#define HM_WU2  45056
#define HM_RED  49152
#define HM_SMEM 50176
#define HMS 40

__global__ void __launch_bounds__(256) k_head_mma(
    const float* __restrict__ bu1, const float* __restrict__ Wu2,
    const float* __restrict__ bu2, float* __restrict__ out)
{
    extern __shared__ char smc[];
    uint32_t sb = smem_u32(smc);
    int tid = threadIdx.x, wid = tid >> 5, lane = tid & 31;
    int warp_m = wid & 3, warp_n = wid >> 2;

    float* sbu1 = (float*)(smc + HM_BU1);
    float* sWu2 = (float*)(smc + HM_WU2);
    float* sRed = (float*)(smc + HM_RED);
    for (int i = tid; i < 1024; i += 256) { sbu1[i] = bu1[i]; sWu2[i] = Wu2[i]; }

    int r0 = blockIdx.x * 128;
    float orow[4] = {0.0f, 0.0f, 0.0f, 0.0f};

    int lm_r = (lane & 7) + ((lane >> 3) & 1) * 8;
    int lm_k = (lane >> 4) * 8;
    int lb_r = (lane & 7) + ((lane >> 4) & 1) * 8;
    int lb_k = ((lane >> 3) & 1) * 8;

    for (int jt = 0; jt < 8; jt++) {
        int j0 = jt * 128;
        float acc[2][8][4];
        #pragma unroll
        for (int mi = 0; mi < 2; mi++)
            #pragma unroll
            for (int ni = 0; ni < 8; ni++)
                #pragma unroll
                for (int e = 0; e < 4; e++) acc[mi][ni][e] = 0.0f;

        for (int kc = 0; kc < 32; kc++) {
            int k0 = kc * 32;
            #pragma unroll
            for (int v = 0; v < 2; v++) {
                int idx = tid + v * 256;
                int r = idx >> 2, k8 = idx & 3;
                uint32_t so = (uint32_t)(r * (HMS * 2) + k8 * 16);
                size_t ga = (size_t)(r0 + r) * 1024 + k0 + k8 * 8;
                size_t gb = (size_t)(j0 + r) * 1024 + k0 + k8 * 8;
                *(uint4*)(smc + HM_SAH + so) = *(const uint4*)&g_xu_hi[ga];
                *(uint4*)(smc + HM_SAL + so) = *(const uint4*)&g_xu_lo[ga];
                *(uint4*)(smc + HM_SBH + so) = *(const uint4*)&g_w1t_hi[gb];
                *(uint4*)(smc + HM_SBL + so) = *(const uint4*)&g_w1t_lo[gb];
            }
            __syncthreads();

            #pragma unroll
            for (int k16 = 0; k16 < 2; k16++) {
                int ko = k16 * 16;
                uint32_t ah[2][4], bh[8][2];
                #pragma unroll
                for (int mi = 0; mi < 2; mi++) {
                    uint32_t addr = sb + HM_SAH +
                        (uint32_t)(((warp_m * 32 + mi * 16 + lm_r) * HMS + ko + lm_k) * 2);
                    ldm_x4(ah[mi], addr);
                }
                #pragma unroll
                for (int n2 = 0; n2 < 4; n2++) {
                    uint32_t r4[4];
                    uint32_t addr = sb + HM_SBH +
                        (uint32_t)(((warp_n * 64 + n2 * 16 + lb_r) * HMS + ko + lb_k) * 2);
                    ldm_x4(r4, addr);
                    bh[n2 * 2][0] = r4[0]; bh[n2 * 2][1] = r4[1];
                    bh[n2 * 2 + 1][0] = r4[2]; bh[n2 * 2 + 1][1] = r4[3];
                }
                #pragma unroll
                for (int mi = 0; mi < 2; mi++)
                    #pragma unroll
                    for (int ni = 0; ni < 8; ni++)
                        mma_bf16(acc[mi][ni], ah[mi], bh[ni]);
                {
                    uint32_t al[2][4];
                    #pragma unroll
                    for (int mi = 0; mi < 2; mi++) {
                        uint32_t addr = sb + HM_SAL +
                            (uint32_t)(((warp_m * 32 + mi * 16 + lm_r) * HMS + ko + lm_k) * 2);
                        ldm_x4(al[mi], addr);
                    }
                    #pragma unroll
                    for (int mi = 0; mi < 2; mi++)
                        #pragma unroll
                        for (int ni = 0; ni < 8; ni++)
                            mma_bf16(acc[mi][ni], al[mi], bh[ni]);
                }
                {
                    uint32_t bl[8][2];
                    #pragma unroll
                    for (int n2 = 0; n2 < 4; n2++) {
                        uint32_t r4[4];
                        uint32_t addr = sb + HM_SBL +
                            (uint32_t)(((warp_n * 64 + n2 * 16 + lb_r) * HMS + ko + lb_k) * 2);
                        ldm_x4(r4, addr);
                        bl[n2 * 2][0] = r4[0]; bl[n2 * 2][1] = r4[1];
                        bl[n2 * 2 + 1][0] = r4[2]; bl[n2 * 2 + 1][1] = r4[3];
                    }
                    #pragma unroll
                    for (int mi = 0; mi < 2; mi++)
                        #pragma unroll
                        for (int ni = 0; ni < 8; ni++)
                            mma_bf16(acc[mi][ni], ah[mi], bl[ni]);
                }
            }
            __syncthreads();
        }

        #pragma unroll
        for (int mi = 0; mi < 2; mi++)
            #pragma unroll
            for (int ni = 0; ni < 8; ni++)
                #pragma unroll
                for (int e = 0; e < 4; e++) {
                    int j = j0 + warp_n * 64 + ni * 8 + (lane & 3) * 2 + (e & 1);
                    float h = acc[mi][ni][e] + sbu1[j];
                    h = (h >= 0.0f) ? h : 0.2f * h;
                    orow[mi * 2 + (e >> 1)] = fmaf(sWu2[j], h, orow[mi * 2 + (e >> 1)]);
                }
    }

    #pragma unroll
    for (int r4 = 0; r4 < 4; r4++) {
        float v = orow[r4];
        v += __shfl_xor_sync(0xffffffffu, v, 1);
        v += __shfl_xor_sync(0xffffffffu, v, 2);
        orow[r4] = v;
    }
    if ((lane & 3) == 0) {
        #pragma unroll
        for (int r4 = 0; r4 < 4; r4++) {
            int row = warp_m * 32 + (r4 >> 1) * 16 + (r4 & 1) * 8 + (lane >> 2);
            sRed[row * 2 + warp_n] = orow[r4];
        }
    }
    __syncthreads();
    if (tid < 128) {
        float s = sRed[tid * 2] + sRed[tid * 2 + 1] + __ldg(&bu2[0]);
        out[r0 + tid] = (s >= 0.0f) ? s : 0.2f * s;
    }
}

// =========================================================================
// launch
// =========================================================================
extern "C" void kernel_launch(void* const* d_in, const int* in_sizes, int n_in,
                              void* d_out, int out_size)
{
    const float* x       = (const float*)d_in[0];
    const float* coords1 = (const float*)d_in[1];
    const float* coords2 = (const float*)d_in[2];
    const float* g1      = (const float*)d_in[3];
    const float* be1     = (const float*)d_in[4];
    const float* Wq      = (const float*)d_in[5];
    const float* bq      = (const float*)d_in[6];
    const float* Wk      = (const float*)d_in[7];
    const float* bk      = (const float*)d_in[8];
    const float* Wv      = (const float*)d_in[9];
    const float* bv      = (const float*)d_in[10];
    const float* ls      = (const float*)d_in[11];
    const float* Wo      = (const float*)d_in[12];
    const float* bo      = (const float*)d_in[13];
    const float* Wp1     = (const float*)d_in[14];
    const float* bp1     = (const float*)d_in[15];
    const float* Wp2     = (const float*)d_in[16];
    const float* bp2     = (const float*)d_in[17];
    const float* g2      = (const float*)d_in[18];
    const float* be2     = (const float*)d_in[19];
    const float* Wn1     = (const float*)d_in[20];
    const float* bn1     = (const float*)d_in[21];
    const float* Wn2     = (const float*)d_in[22];
    const float* bn2     = (const float*)d_in[23];
    const float* g3      = (const float*)d_in[24];
    const float* be3     = (const float*)d_in[25];
    const float* Wu1     = (const float*)d_in[26];
    const float* bu1     = (const float*)d_in[27];
    const float* Wu2     = (const float*)d_in[28];
    const float* bu2     = (const float*)d_in[29];
    float* out = (float*)d_out;

    cudaFuncSetAttribute(k_attn_mma, cudaFuncAttributeMaxDynamicSharedMemorySize,
                         AT_SMEM);
    cudaFuncSetAttribute(k_head_mma, cudaFuncAttributeMaxDynamicSharedMemorySize,
                         HM_SMEM);

    k_ln1 <<<BT_ / 8, 256>>>(x, g1, be1);
    k_topk<<<T_ / 4, 128>>>(coords1, coords2);
    k_bias<<<T_, 256>>>(Wp1, bp1, Wp2, bp2);
    k_split<<<dim3(32, 32), 256>>>(Wu1);
    k_prep_w<<<5, 256>>>(Wq, Wk, Wv, Wo, Wn1);
    k_attn_mma<<<148, 256, AT_SMEM>>>(bq, bk, bv, ls, bo, g2, be2,
                                      bn1, Wn2, bn2, g3, be3);
    k_head_mma<<<BT_ / 128, 256, HM_SMEM>>>(bu1, Wu2, bu2, out);
}